// round 5
// baseline (speedup 1.0000x reference)
#include <cuda_runtime.h>

#define Nn   1024
#define Cc   64
#define HID  128
#define TS   16                          // output unit edge
#define NTS  (Nn / TS)                   // 64
#define NUNITS (NTS * (NTS + 1) / 2)     // 2080

// interleaved: g_p[h*Nn + n] = (pi[h,n], pj[h,n])
__device__ float2 g_p[HID * Nn];

__device__ __forceinline__ float tanh_apx(float x) {
    float y;
    asm("tanh.approx.f32 %0, %1;" : "=f"(y) : "f"(x));
    return y;
}

// ---------------------------------------------------------------------------
// prep: pi[h,n] = sum_c W1[h,Cc+c]*tanh(x[c,n]) + b1[h]
//       pj[h,n] = sum_c W1[h,   c]*tanh(x[c,n])
// grid 128 blocks x 256 threads; block = 8-col n chunk;
// thread = (h = tid&127, ngroup = tid>>7 of 4 cols)
// ---------------------------------------------------------------------------
#define NCH 8
__global__ __launch_bounds__(256) void prep_kernel(const float* __restrict__ x,
                                                   const float* __restrict__ W1,
                                                   const float* __restrict__ b1) {
    __shared__ float t_s[Cc][NCH];
    const int n0  = blockIdx.x * NCH;
    const int tid = threadIdx.x;

    for (int k = tid; k < Cc * NCH; k += 256) {
        int c = k / NCH, n = k % NCH;
        t_s[c][n] = tanhf(x[c * Nn + n0 + n]);   // precise tanh in pre-pass
    }
    __syncthreads();

    const int h  = tid & 127;
    const int ng = (tid >> 7) * 4;     // 0 or 4
    float accj[4], acci[4];
    const float bb = b1[h];
#pragma unroll
    for (int n = 0; n < 4; n++) { accj[n] = 0.0f; acci[n] = bb; }

#pragma unroll
    for (int c = 0; c < Cc; c++) {
        float wj = W1[h * (2 * Cc) + c];
        float wi = W1[h * (2 * Cc) + Cc + c];
#pragma unroll
        for (int n = 0; n < 4; n++) {
            float t = t_s[c][ng + n];
            accj[n] = fmaf(wj, t, accj[n]);
            acci[n] = fmaf(wi, t, acci[n]);
        }
    }
#pragma unroll
    for (int n = 0; n < 4; n++)
        g_p[h * Nn + n0 + ng + n] = make_float2(acci[n], accj[n]);
}

// ---------------------------------------------------------------------------
// pair: triangular unit (a <= b): i in [16a,16a+16), j in [16b,16b+16).
// 128 threads, each owns 1 i x 2 j:
//   acc_B = sum_h w2[h]*( tanh(pi_i + pj_jB) + tanh(pi_jB + pj_i) )
//   out[i,jB] = out[jB,i] = acc_B + 2*b2
// Single shared stage of all 128 h (one __syncthreads).
// ---------------------------------------------------------------------------
__global__ __launch_bounds__(128) void pair_kernel(const float* __restrict__ W2,
                                                   const float* __restrict__ b2,
                                                   float* __restrict__ out) {
    __shared__ __align__(16) float2 pS[HID][2 * TS];  // [h][0..15]=i cols, [16..31]=j cols
    __shared__ float w2s[HID];

    // triangular decode
    int rem = blockIdx.x, a = 0, len = NTS;
    while (rem >= len) { rem -= len; a++; len--; }
    const int b  = a + rem;
    const int i0 = a * TS, j0 = b * TS;

    const int tid = threadIdx.x;
    if (tid < HID) w2s[tid] = W2[tid];

    // stage: 128 h x (16 i-cols + 16 j-cols) float2 = 2048 float4, 16/thread
    for (int t = tid; t < HID * 16; t += 128) {
        int h    = t >> 4;
        int q    = t & 15;
        int side = q >> 3;             // 0 = i-side, 1 = j-side
        int c2   = (q & 7) * 2;        // float2 col within side
        int base = side ? j0 : i0;
        float4 v = *(const float4*)&g_p[h * Nn + base + c2];
        *(float4*)&pS[h][side * TS + c2] = v;
    }
    __syncthreads();

    const int ii  = tid >> 3;      // 0..15
    const int jj2 = tid & 7;       // 0..7 (pair of j)

    float acc0 = 0.0f, acc1 = 0.0f;

#pragma unroll 8
    for (int h = 0; h < HID; h++) {
        float2 ai = pS[h][ii];                          // (pi_i, pj_i)
        float4 aj = *(const float4*)&pS[h][TS + jj2*2]; // (pi_j0,pj_j0,pi_j1,pj_j1)
        float  w  = w2s[h];
        acc0 = fmaf(w, tanh_apx(ai.x + aj.y) + tanh_apx(aj.x + ai.y), acc0);
        acc1 = fmaf(w, tanh_apx(ai.x + aj.w) + tanh_apx(aj.z + ai.y), acc1);
    }

    const float bb2 = 2.0f * b2[0];
    const float v0 = acc0 + bb2, v1 = acc1 + bb2;
    const int gi = i0 + ii;
    const int gj = j0 + jj2 * 2;

    *(float2*)&out[gi * Nn + gj] = make_float2(v0, v1);  // upper tile, coalesced
    out[(gj + 0) * Nn + gi] = v0;                        // mirror
    out[(gj + 1) * Nn + gi] = v1;
}

extern "C" void kernel_launch(void* const* d_in, const int* in_sizes, int n_in,
                              void* d_out, int out_size) {
    const float* x  = (const float*)d_in[0];
    const float* W1 = (const float*)d_in[1];
    const float* b1 = (const float*)d_in[2];
    const float* W2 = (const float*)d_in[3];
    const float* b2 = (const float*)d_in[4];
    float* out = (float*)d_out;

    prep_kernel<<<Nn / NCH, 256>>>(x, W1, b1);
    pair_kernel<<<NUNITS, 128>>>(W2, b2, out);
}